// round 13
// baseline (speedup 1.0000x reference)
#include <cuda_runtime.h>
#include <cuda_fp16.h>
#include <cstdint>

#define BB   16
#define TT   4096
#define CC   256
#define NCH  256          // chunks per scan
#define CLEN 16           // T / NCH
#define SG   16           // supergroups (16 chunks each)
#define NELEM (BB*TT*CC)
#define NAGG  (BB*NCH*CC)
#define NSUP  (BB*SG*CC)

__device__ __half g_xsh[NELEM];    // omni output, fp16 (GEMM0 A)
__device__ __half g_pv [NELEM];    // fused sr*v product, fp16 (GEMM1 A)
__device__ __half g_whT[4 * 65536];// transposed fp16 weights [w][n][k]
__device__ float  g_k  [NELEM];    // fp32: lives in the exponent
__device__ __half g_vh [NELEM];    // fp16 v
__device__ __half g_srh[NELEM];    // fp16 sigmoid(r)
// chunk-level aggregates and intra-super exclusive prefixes/suffixes
__device__ float g_fA[NAGG], g_fB[NAGG], g_fP[NAGG];
__device__ float g_bAg[NAGG], g_bBg[NAGG], g_bPg[NAGG];
__device__ float g_pA[NAGG], g_pB[NAGG], g_pP[NAGG];
__device__ float g_sA[NAGG], g_sB[NAGG], g_sP[NAGG];
// super-level
__device__ float g_sgA[NSUP], g_sgB[NSUP], g_sgP[NSUP];
__device__ float g_sgbA[NSUP], g_sgbB[NSUP], g_sgbP[NSUP];
__device__ float g_SPA[NSUP], g_SPB[NSUP], g_SPP[NSUP];
__device__ float g_SSA[NSUP], g_SSB[NSUP], g_SSP[NSUP];

__device__ __forceinline__ void mma16(float* c, const uint32_t* a, const uint32_t* b) {
    asm volatile(
        "mma.sync.aligned.m16n8k16.row.col.f32.f16.f16.f32 "
        "{%0,%1,%2,%3}, {%4,%5,%6,%7}, {%8,%9}, {%0,%1,%2,%3};"
        : "+f"(c[0]), "+f"(c[1]), "+f"(c[2]), "+f"(c[3])
        : "r"(a[0]), "r"(a[1]), "r"(a[2]), "r"(a[3]), "r"(b[0]), "r"(b[1]));
}

__device__ __forceinline__ void ldsm4(uint32_t* r, uint32_t saddr) {
    asm volatile("ldmatrix.sync.aligned.m8n8.x4.shared.b16 {%0,%1,%2,%3}, [%4];"
        : "=r"(r[0]), "=r"(r[1]), "=r"(r[2]), "=r"(r[3]) : "r"(saddr));
}
__device__ __forceinline__ void ldsm2(uint32_t* r, uint32_t saddr) {
    asm volatile("ldmatrix.sync.aligned.m8n8.x2.shared.b16 {%0,%1}, [%2];"
        : "=r"(r[0]), "=r"(r[1]) : "r"(saddr));
}

__device__ __forceinline__ void cpa16(uint32_t saddr, const void* gaddr) {
    asm volatile("cp.async.cg.shared.global [%0], [%1], 16;"
                 :: "r"(saddr), "l"(gaddr) : "memory");
}
#define CP_COMMIT() asm volatile("cp.async.commit_group;" ::: "memory")
#define CP_WAIT1()  asm volatile("cp.async.wait_group 1;" ::: "memory")
#define CP_WAIT0()  asm volatile("cp.async.wait_group 0;" ::: "memory")

template<int JM>
__device__ __forceinline__ int seqmap(int s) {
    return (JM == 0) ? s : (((s & 63) << 6) | (s >> 6));
}

// single-exp scan step: q = max(p+sh, kt); one of e1,e2 is 1.
__device__ __forceinline__ void step1(float& a, float& b, float& p,
                                      float sh, float kt, float vt) {
    float d = p + sh - kt;
    float e = __expf(-fabsf(d));
    bool gt = d > 0.0f;
    float e1 = gt ? 1.0f : e;
    float e2 = gt ? e : 1.0f;
    a = e1 * a + e2 * vt;
    b = e1 * b + e2;
    p = gt ? (p + sh) : kt;
}
__device__ __forceinline__ void stepagg(float& a, float& b, float& p, float sh,
                                        float Ag, float Bg, float Pg) {
    float d = p + sh - Pg;
    float e = __expf(-fabsf(d));
    bool gt = d > 0.0f;
    float e1 = gt ? 1.0f : e;
    float e2 = gt ? e : 1.0f;
    a = e1 * a + e2 * Ag;
    b = e1 * b + e2 * Bg;
    p = gt ? (p + sh) : Pg;
}

// ---------------- omni_shift (fp16 output) -----------------------------------
__global__ __launch_bounds__(256) void omni_kernel(
    const float* __restrict__ x, const float* __restrict__ alpha,
    const float* __restrict__ w1, const float* __restrict__ w3,
    const float* __restrict__ w5)
{
    int c = threadIdx.x;
    int b = blockIdx.x >> 6;
    int w = blockIdx.x & 63;
    float a0 = alpha[0], a1 = alpha[1], a2 = alpha[2], a3 = alpha[3];

    float coef[5][5];
    #pragma unroll
    for (int r = 0; r < 5; r++)
        #pragma unroll
        for (int d = 0; d < 5; d++)
            coef[r][d] = a3 * w5[c * 25 + r * 5 + d];
    #pragma unroll
    for (int r = 0; r < 3; r++)
        #pragma unroll
        for (int d = 0; d < 3; d++)
            coef[r + 1][d + 1] += a2 * w3[c * 9 + r * 3 + d];
    coef[2][2] += a0 + a1 * w1[c];

    const float* xb = x + (size_t)b * TT * CC + c;
    __half* ob = g_xsh + (size_t)b * TT * CC + c;

    float win[5][5];
    #pragma unroll
    for (int r = 0; r < 5; r++) {
        int hr = r - 2;
        #pragma unroll
        for (int d = 0; d < 5; d++) {
            int wx = w + d - 2;
            win[r][d] = (hr >= 0 && wx >= 0 && wx < 64) ? xb[(hr * 64 + wx) * CC] : 0.0f;
        }
    }
    for (int h = 0; h < 64; h++) {
        float acc = 0.0f;
        #pragma unroll
        for (int r = 0; r < 5; r++)
            #pragma unroll
            for (int d = 0; d < 5; d++)
                acc = fmaf(coef[r][d], win[r][d], acc);
        ob[(h * 64 + w) * CC] = __float2half_rn(acc);
        #pragma unroll
        for (int r = 0; r < 4; r++)
            #pragma unroll
            for (int d = 0; d < 5; d++)
                win[r][d] = win[r + 1][d];
        int hr = h + 3;
        #pragma unroll
        for (int d = 0; d < 5; d++) {
            int wx = w + d - 2;
            win[4][d] = (hr < 64 && wx >= 0 && wx < 64) ? xb[(hr * 64 + wx) * CC] : 0.0f;
        }
    }
}

// ---------------- weight transpose + fp16 round ------------------------------
__global__ void prep_kernel(const float* __restrict__ W0, const float* __restrict__ W1,
                            const float* __restrict__ W2, const float* __restrict__ W3)
{
    int widx = blockIdx.y;
    int n = blockIdx.x;
    int k = threadIdx.x;
    const float* W = (widx == 0) ? W0 : (widx == 1) ? W1 : (widx == 2) ? W2 : W3;
    g_whT[widx * 65536 + n * 256 + k] = __float2half_rn(W[k * 256 + n]);
}

// ---------------- fp16 mma.sync GEMM, cp.async + ldmatrix --------------------
// smem (halves, row stride 72): A st0 [0,9216) A st1 [9216,18432)
//                               B st0 [18432,27648) B st1 [27648,36864)
// MODE 0: A=g_xsh, bx 0..5 -> {Wk|Wv|Wr} halves -> g_k (fp32) / g_vh / g_srh
// MODE 1: A=g_pv, B=WoT, writes fp32 outp, bx 0..1
template<int MODE>
__global__ __launch_bounds__(256) void gemm_mma(float* __restrict__ outp)
{
    extern __shared__ __half smh[];

    int tid = threadIdx.x;
    int wid = tid >> 5, lane = tid & 31;
    int wm = wid & 1, wn = wid >> 1;
    int qr = lane >> 2, qc = lane & 3;
    int bx = blockIdx.x, by = blockIdx.y;
    int m0 = by * 128;

    int widx, ncol0;
    if (MODE == 0) { widx = bx >> 1; ncol0 = (bx & 1) * 128; }
    else           { widx = 3;       ncol0 = bx * 128; }
    const __half* Asrc = (MODE == 0) ? g_xsh : g_pv;
    const __half* Bw = g_whT + widx * 65536;

    int crow[4], ch8[4];
    uint32_t sAaddr[4], sBaddr[4];
    #pragma unroll
    for (int q = 0; q < 4; q++) {
        int id = tid + q * 256;
        crow[q] = id >> 3;
        ch8[q] = (id & 7) * 8;
        sAaddr[q] = (uint32_t)__cvta_generic_to_shared(&smh[crow[q] * 72 + ch8[q]]);
        sBaddr[q] = (uint32_t)__cvta_generic_to_shared(&smh[18432 + crow[q] * 72 + ch8[q]]);
    }

    // ldmatrix per-lane addressing
    uint32_t smbase = (uint32_t)__cvta_generic_to_shared(smh);
    int arow = (lane & 7) + ((lane >> 3) & 1) * 8;   // row within m16 tile
    int acol = (lane >> 4) * 8;                      // k offset 0 or 8
    int l4 = lane & 15;
    int brow = l4 & 7;                               // row within n8 tile
    int bcol = (l4 >> 3) * 8;                        // k offset 0 or 8

    float acc[4][4][4];
    #pragma unroll
    for (int i = 0; i < 4; i++)
        #pragma unroll
        for (int j = 0; j < 4; j++)
            #pragma unroll
            for (int e = 0; e < 4; e++)
                acc[i][j][e] = 0.0f;

    auto issue = [&](int kt, int st) {
        int k0 = kt * 64;
        uint32_t so = st * 18432;
        #pragma unroll
        for (int q = 0; q < 4; q++) {
            cpa16(sAaddr[q] + so, Asrc + (size_t)(m0 + crow[q]) * CC + k0 + ch8[q]);
            cpa16(sBaddr[q] + so, Bw + (size_t)(ncol0 + crow[q]) * CC + k0 + ch8[q]);
        }
    };

    issue(0, 0);
    CP_COMMIT();

    for (int kt = 0; kt < 4; kt++) {
        int st = kt & 1;
        if (kt + 1 < 4) { issue(kt + 1, st ^ 1); CP_COMMIT(); CP_WAIT1(); }
        else            { CP_WAIT0(); }
        __syncthreads();

        uint32_t aBase = smbase + st * 18432;           // bytes
        uint32_t bBase = smbase + 36864 + st * 18432;   // bytes
        #pragma unroll
        for (int ks = 0; ks < 4; ks++) {
            int kk = ks * 16;
            uint32_t a[4][4], b[4][2];
            #pragma unroll
            for (int mf = 0; mf < 4; mf++) {
                int r = wm * 64 + mf * 16 + arow;
                ldsm4(a[mf], aBase + (uint32_t)((r * 72 + kk + acol) * 2));
            }
            #pragma unroll
            for (int nf = 0; nf < 4; nf++) {
                int n = wn * 32 + nf * 8 + brow;
                ldsm2(b[nf], bBase + (uint32_t)((n * 72 + kk + bcol) * 2));
            }
            #pragma unroll
            for (int mf = 0; mf < 4; mf++)
                #pragma unroll
                for (int nf = 0; nf < 4; nf++)
                    mma16(acc[mf][nf], a[mf], b[nf]);
        }
        __syncthreads();
    }

    // epilogue
    #pragma unroll
    for (int mf = 0; mf < 4; mf++) {
        int row = m0 + wm * 64 + mf * 16 + qr;
        #pragma unroll
        for (int nf = 0; nf < 4; nf++) {
            int col = ncol0 + wn * 32 + nf * 8 + qc * 2;
            float v0 = acc[mf][nf][0], v1 = acc[mf][nf][1];
            float v2 = acc[mf][nf][2], v3 = acc[mf][nf][3];
            if (MODE == 1) {
                *(float2*)&outp[(size_t)row * CC + col]       = make_float2(v0, v1);
                *(float2*)&outp[(size_t)(row + 8) * CC + col] = make_float2(v2, v3);
            } else if (widx == 0) {
                *(float2*)&g_k[(size_t)row * CC + col]       = make_float2(v0, v1);
                *(float2*)&g_k[(size_t)(row + 8) * CC + col] = make_float2(v2, v3);
            } else if (widx == 1) {
                *(__half2*)&g_vh[(size_t)row * CC + col]       = __floats2half2_rn(v0, v1);
                *(__half2*)&g_vh[(size_t)(row + 8) * CC + col] = __floats2half2_rn(v2, v3);
            } else {
                v0 = 1.0f / (1.0f + __expf(-v0));
                v1 = 1.0f / (1.0f + __expf(-v1));
                v2 = 1.0f / (1.0f + __expf(-v2));
                v3 = 1.0f / (1.0f + __expf(-v3));
                *(__half2*)&g_srh[(size_t)row * CC + col]       = __floats2half2_rn(v0, v1);
                *(__half2*)&g_srh[(size_t)(row + 8) * CC + col] = __floats2half2_rn(v2, v3);
            }
        }
    }
}

// ---------------- scan phase 1: chunk aggregates -----------------------------
template<int JM>
__global__ __launch_bounds__(256, 2) void scan_p1(const float* __restrict__ sd, int j)
{
    int c = threadIdx.x;
    int b = blockIdx.x >> 8;
    int ch = blockIdx.x & 255;
    float wneg = -__expf(sd[j * CC + c] * (1.0f / 4096.0f));
    int base = b * TT * CC + c;
    int s0 = ch * CLEN;

    float kk[CLEN], vv[CLEN];
    #pragma unroll
    for (int i = 0; i < CLEN; i++) {
        int t = seqmap<JM>(s0 + i);
        kk[i] = g_k[base + t * CC];
        vv[i] = __half2float(g_vh[base + t * CC]);
    }
    int ai = (b * NCH + ch) * CC + c;

    float a = 0.0f, bb = 0.0f, p = -1e38f;
    #pragma unroll
    for (int i = 0; i < CLEN; i++)
        step1(a, bb, p, wneg, kk[i], vv[i]);
    g_fA[ai] = a; g_fB[ai] = bb; g_fP[ai] = p;

    a = 0.0f; bb = 0.0f; p = -1e38f;
    #pragma unroll
    for (int i = CLEN - 1; i >= 0; i--)
        step1(a, bb, p, wneg, kk[i], vv[i]);
    g_bAg[ai] = a; g_bBg[ai] = bb; g_bPg[ai] = p;
}

// ---------------- scan phase 2a: intra-super prefixes/suffixes + super aggs --
__global__ __launch_bounds__(256) void scan_p2a(const float* __restrict__ sd, int j)
{
    int c = threadIdx.x;
    int bx = blockIdx.x;               // 512 blocks: dir(1) b(4) sg(4)
    int dir = bx >> 8;
    int b = (bx >> 4) & 15;
    int sg = bx & 15;
    float wneg = -__expf(sd[j * CC + c] * (1.0f / 4096.0f));
    float dec = (float)CLEN * wneg;
    int si = (b * SG + sg) * CC + c;
    float a = 0.0f, bb = 0.0f, p = -1e38f;

    if (dir == 0) {
        #pragma unroll
        for (int chl = 0; chl < 16; chl++) {
            int ai = (b * NCH + sg * 16 + chl) * CC + c;
            g_pA[ai] = a; g_pB[ai] = bb; g_pP[ai] = p;
            stepagg(a, bb, p, dec, g_fA[ai], g_fB[ai], g_fP[ai]);
        }
        g_sgA[si] = a; g_sgB[si] = bb; g_sgP[si] = p;
    } else {
        #pragma unroll
        for (int chl = 15; chl >= 0; chl--) {
            int ai = (b * NCH + sg * 16 + chl) * CC + c;
            g_sA[ai] = a; g_sB[ai] = bb; g_sP[ai] = p;
            stepagg(a, bb, p, dec, g_bAg[ai], g_bBg[ai], g_bPg[ai]);
        }
        g_sgbA[si] = a; g_sgbB[si] = bb; g_sgbP[si] = p;
    }
}

// ---------------- scan phase 2b: super-level exclusive scan ------------------
__global__ __launch_bounds__(256) void scan_p2b(const float* __restrict__ sd, int j)
{
    int idx = blockIdx.x * 256 + threadIdx.x;   // 0..8191: dir(1) b(4) c(8)
    int dir = idx >> 12;
    int b = (idx >> 8) & 15;
    int c = idx & 255;
    float wneg = -__expf(sd[j * CC + c] * (1.0f / 4096.0f));
    float dec = (float)(CLEN * 16) * wneg;
    float a = 0.0f, bb = 0.0f, p = -1e38f;

    if (dir == 0) {
        #pragma unroll
        for (int sg = 0; sg < SG; sg++) {
            int si = (b * SG + sg) * CC + c;
            g_SPA[si] = a; g_SPB[si] = bb; g_SPP[si] = p;
            stepagg(a, bb, p, dec, g_sgA[si], g_sgB[si], g_sgP[si]);
        }
    } else {
        #pragma unroll
        for (int sg = SG - 1; sg >= 0; sg--) {
            int si = (b * SG + sg) * CC + c;
            g_SSA[si] = a; g_SSB[si] = bb; g_SSP[si] = p;
            stepagg(a, bb, p, dec, g_sgbA[si], g_sgbB[si], g_sgbP[si]);
        }
    }
}

// ---------------- scan phase 3 -----------------------------------------------
// FUSE=0: writes fp16 v. FUSE=1 (final rec): writes fp16 sr*v product to g_pv.
template<int JM, int FUSE>
__global__ __launch_bounds__(256) void scan_p3(
    const float* __restrict__ sd, const float* __restrict__ sf, int j)
{
    __shared__ float shA[CLEN][256];
    __shared__ float shB[CLEN][256];

    int c = threadIdx.x;
    int b = blockIdx.x >> 8;
    int ch = blockIdx.x & 255;
    int sg = ch >> 4, chl = ch & 15;
    float wneg = -__expf(sd[j * CC + c] * (1.0f / 4096.0f));
    float u = sf[j * CC + c] * (1.0f / 4096.0f);
    int base = b * TT * CC + c;
    int ai = (b * NCH + ch) * CC + c;
    int si = (b * SG + sg) * CC + c;
    int s0 = ch * CLEN;

    // full fwd prefix = super prefix (shift chl*16 steps) ⊕ intra prefix
    float af, bf, pf;
    {
        float pa = g_pA[ai], pb = g_pB[ai], pp = g_pP[ai];
        float Sa = g_SPA[si], Sb = g_SPB[si], Sp = g_SPP[si];
        float sh = Sp + (float)(chl * CLEN) * wneg;
        float q = fmaxf(sh, pp);
        float e1 = __expf(sh - q), e2 = __expf(pp - q);
        af = e1 * Sa + e2 * pa; bf = e1 * Sb + e2 * pb; pf = q;
    }
    // full suffix = intra suffix ⊕ super suffix (shift (15-chl)*16 steps)
    float ab, bbv, pbw;
    {
        float sa = g_sA[ai], sb = g_sB[ai], sp = g_sP[ai];
        float Ta = g_SSA[si], Tb = g_SSB[si], Tp = g_SSP[si];
        float sh = Tp + (float)((15 - chl) * CLEN) * wneg;
        float q = fmaxf(sp, sh);
        float e1 = __expf(sp - q), e2 = __expf(sh - q);
        ab = e1 * sa + e2 * Ta; bbv = e1 * sb + e2 * Tb; pbw = q;
    }

    float kk[CLEN], vv[CLEN];
    #pragma unroll
    for (int i = 0; i < CLEN; i++) {
        int t = seqmap<JM>(s0 + i);
        kk[i] = g_k[base + t * CC];
        vv[i] = __half2float(g_vh[base + t * CC]);
    }

    // forward pass: record pre-update fwd carries (A,B in smem, P in regs)
    float fP[CLEN];
    #pragma unroll
    for (int i = 0; i < CLEN; i++) {
        shA[i][c] = af; shB[i][c] = bf; fP[i] = pf;
        step1(af, bf, pf, wneg, kk[i], vv[i]);
    }

    // backward pass: combine fwd + running bwd + self, then fold element in
    #pragma unroll
    for (int i = CLEN - 1; i >= 0; i--) {
        int t = seqmap<JM>(s0 + i);
        int ti = base + t * CC;
        float ps = u + kk[i];
        float q = fmaxf(fmaxf(fP[i], pbw), ps);
        float ef = __expf(fP[i] - q);
        float eb = __expf(pbw - q);
        float es = __expf(ps - q);
        float num = ef * shA[i][c] + eb * ab + es * vv[i];
        float den = ef * shB[i][c] + eb * bbv + es;
        float r = num / den;
        if (FUSE) {
            g_pv[ti] = __float2half_rn(__half2float(g_srh[ti]) * r);
        } else {
            g_vh[ti] = __float2half_rn(r);
        }
        step1(ab, bbv, pbw, wneg, kk[i], vv[i]);
    }
}

// ---------------- launcher ---------------------------------------------------
extern "C" void kernel_launch(void* const* d_in, const int* in_sizes, int n_in,
                              void* d_out, int out_size)
{
    const float *x = nullptr, *alpha = nullptr, *w1 = nullptr, *w3 = nullptr, *w5 = nullptr;
    const float* Wm[4] = {nullptr, nullptr, nullptr, nullptr};
    const float* S2[2] = {nullptr, nullptr};
    int nW = 0, nS = 0;
    for (int i = 0; i < n_in; i++) {
        int sz = in_sizes[i];
        const float* p = (const float*)d_in[i];
        if      (sz == NELEM) x = p;
        else if (sz == 4)     alpha = p;
        else if (sz == 256)   w1 = p;
        else if (sz == 2304)  w3 = p;
        else if (sz == 6400)  w5 = p;
        else if (sz == 65536) { if (nW < 4) Wm[nW++] = p; }
        else if (sz == 512)   { if (nS < 2) S2[nS++] = p; }
    }

    const int GSMEM = 36864 * 2;   // 73,728 B: 2-stage A+B fp16 tiles
    cudaFuncSetAttribute(gemm_mma<0>, cudaFuncAttributeMaxDynamicSharedMemorySize, GSMEM);
    cudaFuncSetAttribute(gemm_mma<1>, cudaFuncAttributeMaxDynamicSharedMemorySize, GSMEM);

    omni_kernel<<<BB * 64, 256>>>(x, alpha, w1, w3, w5);
    prep_kernel<<<dim3(256, 4), 256>>>(Wm[0], Wm[1], Wm[2], Wm[3]);

    gemm_mma<0><<<dim3(6, 512), 256, GSMEM>>>(nullptr);

    scan_p1<0><<<BB * NCH, 256>>>(S2[0], 0);
    scan_p2a<<<512, 256>>>(S2[0], 0);
    scan_p2b<<<32, 256>>>(S2[0], 0);
    scan_p3<0, 0><<<BB * NCH, 256>>>(S2[0], S2[1], 0);

    scan_p1<1><<<BB * NCH, 256>>>(S2[0], 1);
    scan_p2a<<<512, 256>>>(S2[0], 1);
    scan_p2b<<<32, 256>>>(S2[0], 1);
    scan_p3<1, 1><<<BB * NCH, 256>>>(S2[0], S2[1], 1);

    gemm_mma<1><<<dim3(2, 512), 256, GSMEM>>>((float*)d_out);
}

// round 16
// speedup vs baseline: 1.0147x; 1.0147x over previous
#include <cuda_runtime.h>
#include <cuda_fp16.h>
#include <cstdint>

#define BB   16
#define TT   4096
#define CC   256
#define NCH  256          // chunks per scan
#define CLEN 16           // T / NCH
#define SG   16           // supergroups (16 chunks each)
#define NELEM (BB*TT*CC)
#define NAGG  (BB*NCH*CC)
#define NSUP  (BB*SG*CC)

__device__ __half g_xsh[NELEM];    // omni output, fp16 (GEMM0 A)
__device__ __half g_pv [NELEM];    // fused sr*v product, fp16 (GEMM1 A)
__device__ __half g_whT[4 * 65536];// transposed fp16 weights [w][n][k]
__device__ float  g_k  [NELEM];    // fp32: lives in the exponent
__device__ __half g_vh [NELEM];    // fp16 v
__device__ __half g_srh[NELEM];    // fp16 sigmoid(r)
// chunk-level aggregates and intra-super exclusive prefixes/suffixes
__device__ float g_fA[NAGG], g_fB[NAGG], g_fP[NAGG];
__device__ float g_bAg[NAGG], g_bBg[NAGG], g_bPg[NAGG];
__device__ float g_pA[NAGG], g_pB[NAGG], g_pP[NAGG];
__device__ float g_sA[NAGG], g_sB[NAGG], g_sP[NAGG];
// super-level
__device__ float g_sgA[NSUP], g_sgB[NSUP], g_sgP[NSUP];
__device__ float g_sgbA[NSUP], g_sgbB[NSUP], g_sgbP[NSUP];
__device__ float g_SPA[NSUP], g_SPB[NSUP], g_SPP[NSUP];
__device__ float g_SSA[NSUP], g_SSB[NSUP], g_SSP[NSUP];

__device__ __forceinline__ void mma16(float* c, const uint32_t* a, const uint32_t* b) {
    asm volatile(
        "mma.sync.aligned.m16n8k16.row.col.f32.f16.f16.f32 "
        "{%0,%1,%2,%3}, {%4,%5,%6,%7}, {%8,%9}, {%0,%1,%2,%3};"
        : "+f"(c[0]), "+f"(c[1]), "+f"(c[2]), "+f"(c[3])
        : "r"(a[0]), "r"(a[1]), "r"(a[2]), "r"(a[3]), "r"(b[0]), "r"(b[1]));
}

__device__ __forceinline__ void cpa16(uint32_t saddr, const void* gaddr) {
    asm volatile("cp.async.cg.shared.global [%0], [%1], 16;"
                 :: "r"(saddr), "l"(gaddr) : "memory");
}
#define CP_COMMIT() asm volatile("cp.async.commit_group;" ::: "memory")
#define CP_WAIT1()  asm volatile("cp.async.wait_group 1;" ::: "memory")
#define CP_WAIT0()  asm volatile("cp.async.wait_group 0;" ::: "memory")

template<int JM>
__device__ __forceinline__ int seqmap(int s) {
    return (JM == 0) ? s : (((s & 63) << 6) | (s >> 6));
}

// single-exp scan step: q = max(p+sh, kt); one of e1,e2 is 1.
__device__ __forceinline__ void step1(float& a, float& b, float& p,
                                      float sh, float kt, float vt) {
    float d = p + sh - kt;
    float e = __expf(-fabsf(d));
    bool gt = d > 0.0f;
    float e1 = gt ? 1.0f : e;
    float e2 = gt ? e : 1.0f;
    a = e1 * a + e2 * vt;
    b = e1 * b + e2;
    p = gt ? (p + sh) : kt;
}
__device__ __forceinline__ void stepagg(float& a, float& b, float& p, float sh,
                                        float Ag, float Bg, float Pg) {
    float d = p + sh - Pg;
    float e = __expf(-fabsf(d));
    bool gt = d > 0.0f;
    float e1 = gt ? 1.0f : e;
    float e2 = gt ? e : 1.0f;
    a = e1 * a + e2 * Ag;
    b = e1 * b + e2 * Bg;
    p = gt ? (p + sh) : Pg;
}

// ---------------- omni_shift (fp16 output) -----------------------------------
__global__ __launch_bounds__(256) void omni_kernel(
    const float* __restrict__ x, const float* __restrict__ alpha,
    const float* __restrict__ w1, const float* __restrict__ w3,
    const float* __restrict__ w5)
{
    int c = threadIdx.x;
    int b = blockIdx.x >> 6;
    int w = blockIdx.x & 63;
    float a0 = alpha[0], a1 = alpha[1], a2 = alpha[2], a3 = alpha[3];

    float coef[5][5];
    #pragma unroll
    for (int r = 0; r < 5; r++)
        #pragma unroll
        for (int d = 0; d < 5; d++)
            coef[r][d] = a3 * w5[c * 25 + r * 5 + d];
    #pragma unroll
    for (int r = 0; r < 3; r++)
        #pragma unroll
        for (int d = 0; d < 3; d++)
            coef[r + 1][d + 1] += a2 * w3[c * 9 + r * 3 + d];
    coef[2][2] += a0 + a1 * w1[c];

    const float* xb = x + (size_t)b * TT * CC + c;
    __half* ob = g_xsh + (size_t)b * TT * CC + c;

    float win[5][5];
    #pragma unroll
    for (int r = 0; r < 5; r++) {
        int hr = r - 2;
        #pragma unroll
        for (int d = 0; d < 5; d++) {
            int wx = w + d - 2;
            win[r][d] = (hr >= 0 && wx >= 0 && wx < 64) ? xb[(hr * 64 + wx) * CC] : 0.0f;
        }
    }
    for (int h = 0; h < 64; h++) {
        float acc = 0.0f;
        #pragma unroll
        for (int r = 0; r < 5; r++)
            #pragma unroll
            for (int d = 0; d < 5; d++)
                acc = fmaf(coef[r][d], win[r][d], acc);
        ob[(h * 64 + w) * CC] = __float2half_rn(acc);
        #pragma unroll
        for (int r = 0; r < 4; r++)
            #pragma unroll
            for (int d = 0; d < 5; d++)
                win[r][d] = win[r + 1][d];
        int hr = h + 3;
        #pragma unroll
        for (int d = 0; d < 5; d++) {
            int wx = w + d - 2;
            win[4][d] = (hr < 64 && wx >= 0 && wx < 64) ? xb[(hr * 64 + wx) * CC] : 0.0f;
        }
    }
}

// ---------------- weight transpose + fp16 round (split launch) ---------------
__global__ void prep_kernel(const float* __restrict__ Wa, const float* __restrict__ Wb,
                            int wbase)
{
    int widx = wbase + blockIdx.y;
    int n = blockIdx.x;
    int k = threadIdx.x;
    const float* W = (blockIdx.y == 0) ? Wa : Wb;
    g_whT[widx * 65536 + n * 256 + k] = __float2half_rn(W[k * 256 + n]);
}

// ---------------- fp16 mma.sync GEMM, cp.async 2-stage pipeline --------------
// MODE 0: A=g_xsh, bx 0..5 -> {Wk|Wv|Wr} halves -> g_k (fp32) / g_vh / g_srh
// MODE 1: A=g_pv, B=WoT, writes fp32 outp, bx 0..1
template<int MODE>
__global__ __launch_bounds__(256, 2) void gemm_mma(float* __restrict__ outp)
{
    extern __shared__ __half smh[];

    int tid = threadIdx.x;
    int wid = tid >> 5, lane = tid & 31;
    int wm = wid & 1, wn = wid >> 1;
    int qr = lane >> 2, qc = lane & 3;
    int bx = blockIdx.x, by = blockIdx.y;
    int m0 = by * 128;

    int widx, ncol0;
    if (MODE == 0) { widx = bx >> 1; ncol0 = (bx & 1) * 128; }
    else           { widx = 3;       ncol0 = bx * 128; }
    const __half* Asrc = (MODE == 0) ? g_xsh : g_pv;
    const __half* Bw = g_whT + widx * 65536;

    int crow[4], ch8[4];
    uint32_t sAaddr[4], sBaddr[4];
    #pragma unroll
    for (int q = 0; q < 4; q++) {
        int id = tid + q * 256;
        crow[q] = id >> 3;
        ch8[q] = (id & 7) * 8;
        sAaddr[q] = (uint32_t)__cvta_generic_to_shared(&smh[crow[q] * 72 + ch8[q]]);
        sBaddr[q] = (uint32_t)__cvta_generic_to_shared(&smh[18432 + crow[q] * 72 + ch8[q]]);
    }

    float acc[4][4][4];
    #pragma unroll
    for (int i = 0; i < 4; i++)
        #pragma unroll
        for (int j = 0; j < 4; j++)
            #pragma unroll
            for (int e = 0; e < 4; e++)
                acc[i][j][e] = 0.0f;

    auto issue = [&](int kt, int st) {
        int k0 = kt * 64;
        uint32_t so = st * 18432;
        #pragma unroll
        for (int q = 0; q < 4; q++) {
            cpa16(sAaddr[q] + so, Asrc + (size_t)(m0 + crow[q]) * CC + k0 + ch8[q]);
            cpa16(sBaddr[q] + so, Bw + (size_t)(ncol0 + crow[q]) * CC + k0 + ch8[q]);
        }
    };

    issue(0, 0);
    CP_COMMIT();

    for (int kt = 0; kt < 4; kt++) {
        int st = kt & 1;
        if (kt + 1 < 4) { issue(kt + 1, st ^ 1); CP_COMMIT(); CP_WAIT1(); }
        else            { CP_WAIT0(); }
        __syncthreads();

        const __half* Ab = smh + st * 9216;
        const __half* Bb = smh + 18432 + st * 9216;
        #pragma unroll
        for (int ks = 0; ks < 4; ks++) {
            int kk = ks * 16;
            uint32_t a[4][4], b[4][2];
            #pragma unroll
            for (int mf = 0; mf < 4; mf++) {
                int r = wm * 64 + mf * 16 + qr;
                a[mf][0] = *(const uint32_t*)&Ab[r * 72       + kk + 2 * qc    ];
                a[mf][1] = *(const uint32_t*)&Ab[(r + 8) * 72 + kk + 2 * qc    ];
                a[mf][2] = *(const uint32_t*)&Ab[r * 72       + kk + 2 * qc + 8];
                a[mf][3] = *(const uint32_t*)&Ab[(r + 8) * 72 + kk + 2 * qc + 8];
            }
            #pragma unroll
            for (int nf = 0; nf < 4; nf++) {
                int n = wn * 32 + nf * 8 + qr;
                b[nf][0] = *(const uint32_t*)&Bb[n * 72 + kk + 2 * qc    ];
                b[nf][1] = *(const uint32_t*)&Bb[n * 72 + kk + 2 * qc + 8];
            }
            #pragma unroll
            for (int mf = 0; mf < 4; mf++)
                #pragma unroll
                for (int nf = 0; nf < 4; nf++)
                    mma16(acc[mf][nf], a[mf], b[nf]);
        }
        __syncthreads();
    }

    // epilogue
    #pragma unroll
    for (int mf = 0; mf < 4; mf++) {
        int row = m0 + wm * 64 + mf * 16 + qr;
        #pragma unroll
        for (int nf = 0; nf < 4; nf++) {
            int col = ncol0 + wn * 32 + nf * 8 + qc * 2;
            float v0 = acc[mf][nf][0], v1 = acc[mf][nf][1];
            float v2 = acc[mf][nf][2], v3 = acc[mf][nf][3];
            if (MODE == 1) {
                *(float2*)&outp[(size_t)row * CC + col]       = make_float2(v0, v1);
                *(float2*)&outp[(size_t)(row + 8) * CC + col] = make_float2(v2, v3);
            } else if (widx == 0) {
                *(float2*)&g_k[(size_t)row * CC + col]       = make_float2(v0, v1);
                *(float2*)&g_k[(size_t)(row + 8) * CC + col] = make_float2(v2, v3);
            } else if (widx == 1) {
                *(__half2*)&g_vh[(size_t)row * CC + col]       = __floats2half2_rn(v0, v1);
                *(__half2*)&g_vh[(size_t)(row + 8) * CC + col] = __floats2half2_rn(v2, v3);
            } else {
                v0 = 1.0f / (1.0f + __expf(-v0));
                v1 = 1.0f / (1.0f + __expf(-v1));
                v2 = 1.0f / (1.0f + __expf(-v2));
                v3 = 1.0f / (1.0f + __expf(-v3));
                *(__half2*)&g_srh[(size_t)row * CC + col]       = __floats2half2_rn(v0, v1);
                *(__half2*)&g_srh[(size_t)(row + 8) * CC + col] = __floats2half2_rn(v2, v3);
            }
        }
    }
}

// ---------------- scan phase 1: chunk aggregates -----------------------------
template<int JM>
__global__ __launch_bounds__(256, 2) void scan_p1(const float* __restrict__ sd, int j)
{
    int c = threadIdx.x;
    int b = blockIdx.x >> 8;
    int ch = blockIdx.x & 255;
    float wneg = -__expf(sd[j * CC + c] * (1.0f / 4096.0f));
    int base = b * TT * CC + c;
    int s0 = ch * CLEN;

    float kk[CLEN], vv[CLEN];
    #pragma unroll
    for (int i = 0; i < CLEN; i++) {
        int t = seqmap<JM>(s0 + i);
        kk[i] = g_k[base + t * CC];
        vv[i] = __half2float(g_vh[base + t * CC]);
    }
    int ai = (b * NCH + ch) * CC + c;

    float a = 0.0f, bb = 0.0f, p = -1e38f;
    #pragma unroll
    for (int i = 0; i < CLEN; i++)
        step1(a, bb, p, wneg, kk[i], vv[i]);
    g_fA[ai] = a; g_fB[ai] = bb; g_fP[ai] = p;

    a = 0.0f; bb = 0.0f; p = -1e38f;
    #pragma unroll
    for (int i = CLEN - 1; i >= 0; i--)
        step1(a, bb, p, wneg, kk[i], vv[i]);
    g_bAg[ai] = a; g_bBg[ai] = bb; g_bPg[ai] = p;
}

// ---------------- scan phase 2a: intra-super prefixes/suffixes + super aggs --
__global__ __launch_bounds__(256) void scan_p2a(const float* __restrict__ sd, int j)
{
    int c = threadIdx.x;
    int bx = blockIdx.x;               // 512 blocks: dir(1) b(4) sg(4)
    int dir = bx >> 8;
    int b = (bx >> 4) & 15;
    int sg = bx & 15;
    float wneg = -__expf(sd[j * CC + c] * (1.0f / 4096.0f));
    float dec = (float)CLEN * wneg;
    int si = (b * SG + sg) * CC + c;
    float a = 0.0f, bb = 0.0f, p = -1e38f;

    if (dir == 0) {
        #pragma unroll
        for (int chl = 0; chl < 16; chl++) {
            int ai = (b * NCH + sg * 16 + chl) * CC + c;
            g_pA[ai] = a; g_pB[ai] = bb; g_pP[ai] = p;
            stepagg(a, bb, p, dec, g_fA[ai], g_fB[ai], g_fP[ai]);
        }
        g_sgA[si] = a; g_sgB[si] = bb; g_sgP[si] = p;
    } else {
        #pragma unroll
        for (int chl = 15; chl >= 0; chl--) {
            int ai = (b * NCH + sg * 16 + chl) * CC + c;
            g_sA[ai] = a; g_sB[ai] = bb; g_sP[ai] = p;
            stepagg(a, bb, p, dec, g_bAg[ai], g_bBg[ai], g_bPg[ai]);
        }
        g_sgbA[si] = a; g_sgbB[si] = bb; g_sgbP[si] = p;
    }
}

// ---------------- scan phase 2b: super-level exclusive scan ------------------
__global__ __launch_bounds__(256) void scan_p2b(const float* __restrict__ sd, int j)
{
    int idx = blockIdx.x * 256 + threadIdx.x;   // 0..8191: dir(1) b(4) c(8)
    int dir = idx >> 12;
    int b = (idx >> 8) & 15;
    int c = idx & 255;
    float wneg = -__expf(sd[j * CC + c] * (1.0f / 4096.0f));
    float dec = (float)(CLEN * 16) * wneg;
    float a = 0.0f, bb = 0.0f, p = -1e38f;

    if (dir == 0) {
        #pragma unroll
        for (int sg = 0; sg < SG; sg++) {
            int si = (b * SG + sg) * CC + c;
            g_SPA[si] = a; g_SPB[si] = bb; g_SPP[si] = p;
            stepagg(a, bb, p, dec, g_sgA[si], g_sgB[si], g_sgP[si]);
        }
    } else {
        #pragma unroll
        for (int sg = SG - 1; sg >= 0; sg--) {
            int si = (b * SG + sg) * CC + c;
            g_SSA[si] = a; g_SSB[si] = bb; g_SSP[si] = p;
            stepagg(a, bb, p, dec, g_sgbA[si], g_sgbB[si], g_sgbP[si]);
        }
    }
}

// ---------------- scan phase 3 -----------------------------------------------
// FUSE=0: writes fp16 v. FUSE=1 (final rec): writes fp16 sr*v product to g_pv.
template<int JM, int FUSE>
__global__ __launch_bounds__(256) void scan_p3(
    const float* __restrict__ sd, const float* __restrict__ sf, int j)
{
    __shared__ float shA[CLEN][256];
    __shared__ float shB[CLEN][256];

    int c = threadIdx.x;
    int b = blockIdx.x >> 8;
    int ch = blockIdx.x & 255;
    int sg = ch >> 4, chl = ch & 15;
    float wneg = -__expf(sd[j * CC + c] * (1.0f / 4096.0f));
    float u = sf[j * CC + c] * (1.0f / 4096.0f);
    int base = b * TT * CC + c;
    int ai = (b * NCH + ch) * CC + c;
    int si = (b * SG + sg) * CC + c;
    int s0 = ch * CLEN;

    // full fwd prefix = super prefix (shift chl*16 steps) ⊕ intra prefix
    float af, bf, pf;
    {
        float pa = g_pA[ai], pb = g_pB[ai], pp = g_pP[ai];
        float Sa = g_SPA[si], Sb = g_SPB[si], Sp = g_SPP[si];
        float sh = Sp + (float)(chl * CLEN) * wneg;
        float q = fmaxf(sh, pp);
        float e1 = __expf(sh - q), e2 = __expf(pp - q);
        af = e1 * Sa + e2 * pa; bf = e1 * Sb + e2 * pb; pf = q;
    }
    // full suffix = intra suffix ⊕ super suffix (shift (15-chl)*16 steps)
    float ab, bbv, pbw;
    {
        float sa = g_sA[ai], sb = g_sB[ai], sp = g_sP[ai];
        float Ta = g_SSA[si], Tb = g_SSB[si], Tp = g_SSP[si];
        float sh = Tp + (float)((15 - chl) * CLEN) * wneg;
        float q = fmaxf(sp, sh);
        float e1 = __expf(sp - q), e2 = __expf(sh - q);
        ab = e1 * sa + e2 * Ta; bbv = e1 * sb + e2 * Tb; pbw = q;
    }

    float kk[CLEN], vv[CLEN];
    #pragma unroll
    for (int i = 0; i < CLEN; i++) {
        int t = seqmap<JM>(s0 + i);
        kk[i] = g_k[base + t * CC];
        vv[i] = __half2float(g_vh[base + t * CC]);
    }

    // forward pass: record pre-update fwd carries (A,B in smem, P in regs)
    float fP[CLEN];
    #pragma unroll
    for (int i = 0; i < CLEN; i++) {
        shA[i][c] = af; shB[i][c] = bf; fP[i] = pf;
        step1(af, bf, pf, wneg, kk[i], vv[i]);
    }

    // backward pass: combine fwd + running bwd + self, then fold element in
    #pragma unroll
    for (int i = CLEN - 1; i >= 0; i--) {
        int t = seqmap<JM>(s0 + i);
        int ti = base + t * CC;
        float ps = u + kk[i];
        float q = fmaxf(fmaxf(fP[i], pbw), ps);
        float ef = __expf(fP[i] - q);
        float eb = __expf(pbw - q);
        float es = __expf(ps - q);
        float num = ef * shA[i][c] + eb * ab + es * vv[i];
        float den = ef * shB[i][c] + eb * bbv + es;
        float r = num / den;
        if (FUSE) {
            g_pv[ti] = __float2half_rn(__half2float(g_srh[ti]) * r);
        } else {
            g_vh[ti] = __float2half_rn(r);
        }
        step1(ab, bbv, pbw, wneg, kk[i], vv[i]);
    }
}

// ---------------- launcher ---------------------------------------------------
extern "C" void kernel_launch(void* const* d_in, const int* in_sizes, int n_in,
                              void* d_out, int out_size)
{
    const float *x = nullptr, *alpha = nullptr, *w1 = nullptr, *w3 = nullptr, *w5 = nullptr;
    const float* Wm[4] = {nullptr, nullptr, nullptr, nullptr};
    const float* S2[2] = {nullptr, nullptr};
    int nW = 0, nS = 0;
    for (int i = 0; i < n_in; i++) {
        int sz = in_sizes[i];
        const float* p = (const float*)d_in[i];
        if      (sz == NELEM) x = p;
        else if (sz == 4)     alpha = p;
        else if (sz == 256)   w1 = p;
        else if (sz == 2304)  w3 = p;
        else if (sz == 6400)  w5 = p;
        else if (sz == 65536) { if (nW < 4) Wm[nW++] = p; }
        else if (sz == 512)   { if (nS < 2) S2[nS++] = p; }
    }

    const int GSMEM = 36864 * 2;   // 73,728 B: 2-stage A+B fp16 tiles
    cudaFuncSetAttribute(gemm_mma<0>, cudaFuncAttributeMaxDynamicSharedMemorySize, GSMEM);
    cudaFuncSetAttribute(gemm_mma<1>, cudaFuncAttributeMaxDynamicSharedMemorySize, GSMEM);

    // launches 1-3: omni + split prep  -> gemm_mma<0> is launch #4 (profiled)
    omni_kernel<<<BB * 64, 256>>>(x, alpha, w1, w3, w5);
    prep_kernel<<<dim3(256, 2), 256>>>(Wm[0], Wm[1], 0);
    prep_kernel<<<dim3(256, 2), 256>>>(Wm[2], Wm[3], 2);

    gemm_mma<0><<<dim3(6, 512), 256, GSMEM>>>(nullptr);

    scan_p1<0><<<BB * NCH, 256>>>(S2[0], 0);
    scan_p2a<<<512, 256>>>(S2[0], 0);
    scan_p2b<<<32, 256>>>(S2[0], 0);
    scan_p3<0, 0><<<BB * NCH, 256>>>(S2[0], S2[1], 0);

    scan_p1<1><<<BB * NCH, 256>>>(S2[0], 1);
    scan_p2a<<<512, 256>>>(S2[0], 1);
    scan_p2b<<<32, 256>>>(S2[0], 1);
    scan_p3<1, 1><<<BB * NCH, 256>>>(S2[0], S2[1], 1);

    gemm_mma<1><<<dim3(2, 512), 256, GSMEM>>>((float*)d_out);
}